// round 1
// baseline (speedup 1.0000x reference)
#include <cuda_runtime.h>

// NeighborhoodAttention 3D, NATTEN-style clamped window.
// Static shape: B=1, T=16, H=32, W=32, nh=8, D=128, window (3,7,7).
// Each query attends exactly 3*7*7 = 147 keys:
//   st = clamp(t-1, 0, T-3), sh = clamp(h-3, 0, H-7), sw = clamp(w-3, 0, W-7)
//
// Round-0 baseline: one warp per (query, head). Lanes split D (float4 each).
// Pass 1: 147 scores via per-key dot + butterfly reduce, running max, store
//         unnormalized scores in per-warp smem.
// Softmax: exp(s - m), butterfly sum, normalize at the end.
// Pass 2: PV accumulation (p broadcast from smem, V rows via float4).

#define T_  16
#define H_  32
#define W_  32
#define NH  8
#define DD  128
#define L_  (T_ * H_ * W_)            // 16384
#define NKEYS 147
#define SCALE 0.08838834764831845f    // 1/sqrt(128)

__global__ __launch_bounds__(256, 8)
void na3d_warp_per_query(const float* __restrict__ Q,
                         const float* __restrict__ K,
                         const float* __restrict__ V,
                         float* __restrict__ O)
{
    __shared__ float s_p[8][152];   // per-warp score/prob buffer (147 used)

    const int warp = threadIdx.x >> 5;
    const int lane = threadIdx.x & 31;
    const int wg   = blockIdx.x * 8 + warp;      // global warp id = (head, l)

    const int head = wg >> 14;                   // / L_ (16384)
    const int l    = wg & (L_ - 1);
    const int t    = l >> 10;                    // / (H*W)
    const int h    = (l >> 5) & 31;
    const int w    = l & 31;

    const int st = min(max(t - 1, 0), T_ - 3);
    const int sh = min(max(h - 3, 0), H_ - 7);
    const int sw = min(max(w - 3, 0), W_ - 7);

    const float4* __restrict__ Q4 = (const float4*)Q;
    const float4* __restrict__ K4 = (const float4*)K;
    const float4* __restrict__ V4 = (const float4*)V;
    float4* __restrict__ O4 = (float4*)O;

    // float element base = l*nh*D + head*D + 4*lane ; as float4 index:
    const int qbase4 = l * (NH * DD / 4) + head * (DD / 4) + lane; // l*256 + head*32 + lane
    const float4 qv = Q4[qbase4];

    float* sp = s_p[warp];

    // ---- Pass 1: scores ----
    float m = -1e30f;
    int kidx = 0;
#pragma unroll
    for (int it = 0; it < 3; ++it) {
#pragma unroll
        for (int ih = 0; ih < 7; ++ih) {
            const int rowl = (st + it) * (H_ * W_) + (sh + ih) * W_ + sw;
            const int kb4  = rowl * (NH * DD / 4) + head * (DD / 4) + lane;
#pragma unroll
            for (int iw = 0; iw < 7; ++iw) {
                const float4 kk = K4[kb4 + iw * (NH * DD / 4)];
                float part = qv.x * kk.x + qv.y * kk.y + qv.z * kk.z + qv.w * kk.w;
                part += __shfl_xor_sync(0xffffffffu, part, 16);
                part += __shfl_xor_sync(0xffffffffu, part, 8);
                part += __shfl_xor_sync(0xffffffffu, part, 4);
                part += __shfl_xor_sync(0xffffffffu, part, 2);
                part += __shfl_xor_sync(0xffffffffu, part, 1);
                const float s = part * SCALE;
                m = fmaxf(m, s);                 // s uniform across lanes
                if (lane == 0) sp[kidx] = s;
                ++kidx;
            }
        }
    }
    __syncwarp();

    // ---- Softmax (unnormalized exp in smem, sum via butterfly) ----
    float sum = 0.0f;
#pragma unroll
    for (int i = 0; i < 5; ++i) {
        const int idx = lane + i * 32;
        if (idx < NKEYS) {
            const float p = __expf(sp[idx] - m);
            sp[idx] = p;
            sum += p;
        }
    }
    sum += __shfl_xor_sync(0xffffffffu, sum, 16);
    sum += __shfl_xor_sync(0xffffffffu, sum, 8);
    sum += __shfl_xor_sync(0xffffffffu, sum, 4);
    sum += __shfl_xor_sync(0xffffffffu, sum, 2);
    sum += __shfl_xor_sync(0xffffffffu, sum, 1);
    const float inv = 1.0f / sum;
    __syncwarp();

    // ---- Pass 2: PV ----
    float4 acc = make_float4(0.f, 0.f, 0.f, 0.f);
    kidx = 0;
#pragma unroll
    for (int it = 0; it < 3; ++it) {
#pragma unroll
        for (int ih = 0; ih < 7; ++ih) {
            const int rowl = (st + it) * (H_ * W_) + (sh + ih) * W_ + sw;
            const int vb4  = rowl * (NH * DD / 4) + head * (DD / 4) + lane;
#pragma unroll
            for (int iw = 0; iw < 7; ++iw) {
                const float p = sp[kidx];
                const float4 vv = V4[vb4 + iw * (NH * DD / 4)];
                acc.x = fmaf(p, vv.x, acc.x);
                acc.y = fmaf(p, vv.y, acc.y);
                acc.z = fmaf(p, vv.z, acc.z);
                acc.w = fmaf(p, vv.w, acc.w);
                ++kidx;
            }
        }
    }

    acc.x *= inv; acc.y *= inv; acc.z *= inv; acc.w *= inv;
    O4[qbase4] = acc;
}

extern "C" void kernel_launch(void* const* d_in, const int* in_sizes, int n_in,
                              void* d_out, int out_size)
{
    const float* q = (const float*)d_in[0];
    const float* k = (const float*)d_in[1];
    const float* v = (const float*)d_in[2];
    float* out = (float*)d_out;

    // total warps = L * nh = 131072 ; 8 warps per CTA
    const int blocks = (L_ * NH) / 8;   // 16384
    na3d_warp_per_query<<<blocks, 256>>>(q, k, v, out);
}